// round 2
// baseline (speedup 1.0000x reference)
#include <cuda_runtime.h>

#define HIDDEN   1024
#define HEADS    16
#define HEAD_DIM 64
#define BATCH    4
#define SEQ      2048
#define MROWS    (BATCH * SEQ)   /* 8192 */

// Scratch (device globals — no allocation allowed in kernel_launch)
__device__ float g_Q[MROWS * HIDDEN];
__device__ float g_K[MROWS * HIDDEN];
__device__ float g_V[MROWS * HIDDEN];
__device__ float g_M[BATCH * HEADS * HEAD_DIM * HEAD_DIM];  // K^T V per (b,h)

struct ProjArgs {
    const float* X[3];
    const float* W[3];
    const float* Bv[3];
    float*       Y[3];
};

// ---------------------------------------------------------------------------
// Kernel 1: Y = X @ W + b   (M=8192, N=1024, K=1024), z selects q/k/v
// 128x128 tile, BK=8, 8x8 per thread, 256 threads.
// ---------------------------------------------------------------------------
__global__ __launch_bounds__(256, 2)
void proj_gemm(ProjArgs args) {
    const int z = blockIdx.z;
    const float* __restrict__ X  = args.X[z];
    const float* __restrict__ W  = args.W[z];
    const float* __restrict__ Bv = args.Bv[z];
    float* __restrict__       Y  = args.Y[z];

    __shared__ float As[8][128];   // transposed A tile: As[k][m]
    __shared__ float Bs[8][128];   // Bs[k][n]

    const int tid = threadIdx.x;
    const int tx  = tid & 15;      // 0..15
    const int ty  = tid >> 4;      // 0..15
    const int m0  = blockIdx.y * 128;
    const int n0  = blockIdx.x * 128;

    // Global load mapping
    const int a_row = tid >> 1;          // 0..127
    const int a_col = (tid & 1) * 4;     // 0 or 4
    const int b_row = tid >> 5;          // 0..7
    const int b_col = (tid & 31) * 4;    // 0..124

    const float* Aptr = X + (size_t)(m0 + a_row) * HIDDEN + a_col;
    const float* Bptr = W + (size_t)b_row * HIDDEN + n0 + b_col;

    float acc[8][8];
#pragma unroll
    for (int i = 0; i < 8; i++)
#pragma unroll
        for (int j = 0; j < 8; j++) acc[i][j] = 0.0f;

    for (int kt = 0; kt < HIDDEN; kt += 8) {
        float4 av = *reinterpret_cast<const float4*>(Aptr + kt);
        float4 bv = *reinterpret_cast<const float4*>(Bptr + (size_t)kt * HIDDEN);

        As[a_col + 0][a_row] = av.x;
        As[a_col + 1][a_row] = av.y;
        As[a_col + 2][a_row] = av.z;
        As[a_col + 3][a_row] = av.w;
        *reinterpret_cast<float4*>(&Bs[b_row][b_col]) = bv;
        __syncthreads();

#pragma unroll
        for (int kk = 0; kk < 8; kk++) {
            float a[8], b[8];
            *reinterpret_cast<float4*>(&a[0]) = *reinterpret_cast<const float4*>(&As[kk][ty * 4]);
            *reinterpret_cast<float4*>(&a[4]) = *reinterpret_cast<const float4*>(&As[kk][64 + ty * 4]);
            *reinterpret_cast<float4*>(&b[0]) = *reinterpret_cast<const float4*>(&Bs[kk][tx * 4]);
            *reinterpret_cast<float4*>(&b[4]) = *reinterpret_cast<const float4*>(&Bs[kk][64 + tx * 4]);
#pragma unroll
            for (int i = 0; i < 8; i++)
#pragma unroll
                for (int j = 0; j < 8; j++)
                    acc[i][j] = fmaf(a[i], b[j], acc[i][j]);
        }
        __syncthreads();
    }

    // Epilogue: add bias, store (float4 per 4 cols)
#pragma unroll
    for (int i = 0; i < 8; i++) {
        int ri = (i < 4) ? (ty * 4 + i) : (64 + ty * 4 + (i - 4));
        float* yrow = Y + (size_t)(m0 + ri) * HIDDEN + n0;
#pragma unroll
        for (int half = 0; half < 2; half++) {
            int c = half * 64 + tx * 4;
            float4 v;
            v.x = acc[i][half * 4 + 0] + Bv[n0 + c + 0];
            v.y = acc[i][half * 4 + 1] + Bv[n0 + c + 1];
            v.z = acc[i][half * 4 + 2] + Bv[n0 + c + 2];
            v.w = acc[i][half * 4 + 3] + Bv[n0 + c + 3];
            *reinterpret_cast<float4*>(yrow + c) = v;
        }
    }
}

// ---------------------------------------------------------------------------
// Kernel 2: per (b,h), M_h = K_h^T V_h  (64x64, reduction over S=2048)
// One block per (b,h), 256 threads (16x16), 4x4 outputs/thread, s-tiles of 64.
// ---------------------------------------------------------------------------
__global__ __launch_bounds__(256)
void ktv_gemm() {
    const int bh = blockIdx.x;
    const int b  = bh >> 4;
    const int h  = bh & 15;

    const float* Kb = g_K + (size_t)b * SEQ * HIDDEN + h * HEAD_DIM;
    const float* Vb = g_V + (size_t)b * SEQ * HIDDEN + h * HEAD_DIM;

    __shared__ float Ks[64 * 64];
    __shared__ float Vs[64 * 64];

    const int tid = threadIdx.x;
    const int tx  = tid & 15;
    const int ty  = tid >> 4;

    float acc[4][4];
#pragma unroll
    for (int i = 0; i < 4; i++)
#pragma unroll
        for (int j = 0; j < 4; j++) acc[i][j] = 0.0f;

    for (int s0 = 0; s0 < SEQ; s0 += 64) {
        // Load 64x64 tiles (4096 floats each), float4 per thread x4
#pragma unroll
        for (int t = 0; t < 4; t++) {
            int e   = (tid + t * 256) * 4;     // element offset
            int row = e >> 6;
            int col = e & 63;
            *reinterpret_cast<float4*>(&Ks[e]) =
                *reinterpret_cast<const float4*>(Kb + (size_t)(s0 + row) * HIDDEN + col);
            *reinterpret_cast<float4*>(&Vs[e]) =
                *reinterpret_cast<const float4*>(Vb + (size_t)(s0 + row) * HIDDEN + col);
        }
        __syncthreads();

#pragma unroll 4
        for (int ss = 0; ss < 64; ss++) {
            float kv[4], vv[4];
            *reinterpret_cast<float4*>(kv) = *reinterpret_cast<const float4*>(&Ks[ss * 64 + ty * 4]);
            *reinterpret_cast<float4*>(vv) = *reinterpret_cast<const float4*>(&Vs[ss * 64 + tx * 4]);
#pragma unroll
            for (int i = 0; i < 4; i++)
#pragma unroll
                for (int j = 0; j < 4; j++)
                    acc[i][j] = fmaf(kv[i], vv[j], acc[i][j]);
        }
        __syncthreads();
    }

    float* Mh = g_M + (size_t)bh * HEAD_DIM * HEAD_DIM;
#pragma unroll
    for (int i = 0; i < 4; i++) {
        float4 v = make_float4(acc[i][0], acc[i][1], acc[i][2], acc[i][3]);
        *reinterpret_cast<float4*>(&Mh[(ty * 4 + i) * 64 + tx * 4]) = v;
    }
}

// ---------------------------------------------------------------------------
// Kernel 3: out_h = scale * Q_h @ M_h  (per (b,h), tiles of 64 rows)
// grid (SEQ/64, 64bh), 256 threads (16x16), 4x4 outputs/thread.
// ---------------------------------------------------------------------------
__global__ __launch_bounds__(256)
void out_gemm(float* __restrict__ out) {
    const int bh = blockIdx.y;
    const int b  = bh >> 4;
    const int h  = bh & 15;
    const int s0 = blockIdx.x * 64;
    const float scale = 0.125f;   // 1/sqrt(64)

    const float* Qb = g_Q + (size_t)b * SEQ * HIDDEN + h * HEAD_DIM;
    const float* Mh = g_M + (size_t)bh * HEAD_DIM * HEAD_DIM;

    __shared__ float Qs[64 * 64];
    __shared__ float Ms[64 * 64];

    const int tid = threadIdx.x;
    const int tx  = tid & 15;
    const int ty  = tid >> 4;

#pragma unroll
    for (int t = 0; t < 4; t++) {
        int e   = (tid + t * 256) * 4;
        int row = e >> 6;
        int col = e & 63;
        *reinterpret_cast<float4*>(&Qs[e]) =
            *reinterpret_cast<const float4*>(Qb + (size_t)(s0 + row) * HIDDEN + col);
        *reinterpret_cast<float4*>(&Ms[e]) = *reinterpret_cast<const float4*>(&Mh[e]);
    }
    __syncthreads();

    float acc[4][4];
#pragma unroll
    for (int i = 0; i < 4; i++)
#pragma unroll
        for (int j = 0; j < 4; j++) acc[i][j] = 0.0f;

#pragma unroll 4
    for (int k = 0; k < 64; k++) {
        float qv[4], mv[4];
#pragma unroll
        for (int i = 0; i < 4; i++) qv[i] = Qs[(ty * 4 + i) * 64 + k];
        *reinterpret_cast<float4*>(mv) = *reinterpret_cast<const float4*>(&Ms[k * 64 + tx * 4]);
#pragma unroll
        for (int i = 0; i < 4; i++)
#pragma unroll
            for (int j = 0; j < 4; j++)
                acc[i][j] = fmaf(qv[i], mv[j], acc[i][j]);
    }

#pragma unroll
    for (int i = 0; i < 4; i++) {
        float4 v = make_float4(scale * acc[i][0], scale * acc[i][1],
                               scale * acc[i][2], scale * acc[i][3]);
        *reinterpret_cast<float4*>(out + (size_t)(b * SEQ + s0 + ty * 4 + i) * HIDDEN
                                   + h * HEAD_DIM + tx * 4) = v;
    }
}

// ---------------------------------------------------------------------------
extern "C" void kernel_launch(void* const* d_in, const int* in_sizes, int n_in,
                              void* d_out, int out_size) {
    (void)in_sizes; (void)n_in; (void)out_size;
    const float* query = (const float*)d_in[0];
    const float* key   = (const float*)d_in[1];
    const float* value = (const float*)d_in[2];
    const float* q_w   = (const float*)d_in[3];
    const float* q_b   = (const float*)d_in[4];
    const float* k_w   = (const float*)d_in[5];
    const float* k_b   = (const float*)d_in[6];
    const float* v_w   = (const float*)d_in[7];
    const float* v_b   = (const float*)d_in[8];
    float* out = (float*)d_out;

    void *qp, *kp, *vp;
    cudaGetSymbolAddress(&qp, g_Q);
    cudaGetSymbolAddress(&kp, g_K);
    cudaGetSymbolAddress(&vp, g_V);

    ProjArgs args;
    args.X[0] = query; args.X[1] = key;  args.X[2] = value;
    args.W[0] = q_w;   args.W[1] = k_w;  args.W[2] = v_w;
    args.Bv[0] = q_b;  args.Bv[1] = k_b; args.Bv[2] = v_b;
    args.Y[0] = (float*)qp; args.Y[1] = (float*)kp; args.Y[2] = (float*)vp;

    dim3 pgrid(HIDDEN / 128, MROWS / 128, 3);
    proj_gemm<<<pgrid, 256>>>(args);
    ktv_gemm<<<BATCH * HEADS, 256>>>();
    out_gemm<<<dim3(SEQ / 64, BATCH * HEADS), 256>>>(out);
}

// round 4
// speedup vs baseline: 2.0990x; 2.0990x over previous
#include <cuda_runtime.h>
#include <cuda_bf16.h>
#include <cstdint>

#define HIDDEN   1024
#define HEADS    16
#define HEAD_DIM 64
#define BATCH    4
#define SEQ      2048
#define MROWS    (BATCH * SEQ)   /* 8192 */

// ---------------------------------------------------------------------------
// Device-global scratch
// ---------------------------------------------------------------------------
__device__ float g_Q[MROWS * HIDDEN];
__device__ float g_K[MROWS * HIDDEN];
__device__ float g_V[MROWS * HIDDEN];
__device__ float g_M[BATCH * HEADS * HEAD_DIM * HEAD_DIM];

__device__ __nv_bfloat16 g_XHI[3ull * MROWS * HIDDEN];   // X hi ([M][K])
__device__ __nv_bfloat16 g_XLO[3ull * MROWS * HIDDEN];   // X lo
__device__ __nv_bfloat16 g_WHI[3ull * HIDDEN * HIDDEN];  // W^T hi ([N][K])
__device__ __nv_bfloat16 g_WLO[3ull * HIDDEN * HIDDEN];  // W^T lo

// ---------------------------------------------------------------------------
// Helpers (all target-portable: sm_80-class PTX only)
// ---------------------------------------------------------------------------
__device__ __forceinline__ uint32_t smem_u32(const void* p) {
    uint32_t a;
    asm("{ .reg .u64 t; cvta.to.shared.u64 t, %1; cvt.u32.u64 %0, t; }" : "=r"(a) : "l"(p));
    return a;
}
__device__ __forceinline__ void cp16(uint32_t dst, const void* src) {
    asm volatile("cp.async.cg.shared.global [%0], [%1], 16;" :: "r"(dst), "l"(src));
}
#define CP_COMMIT() asm volatile("cp.async.commit_group;" ::: "memory")
#define CP_WAIT1()  asm volatile("cp.async.wait_group 1;"  ::: "memory")

__device__ __forceinline__ void ldsm4(uint32_t (&r)[4], uint32_t addr) {
    asm volatile("ldmatrix.sync.aligned.m8n8.x4.shared.b16 {%0,%1,%2,%3}, [%4];"
                 : "=r"(r[0]), "=r"(r[1]), "=r"(r[2]), "=r"(r[3]) : "r"(addr));
}
__device__ __forceinline__ void mma_bf16(float (&c)[4], const uint32_t (&a)[4],
                                         uint32_t b0, uint32_t b1) {
    asm volatile("mma.sync.aligned.m16n8k16.row.col.f32.bf16.bf16.f32 "
                 "{%0,%1,%2,%3}, {%4,%5,%6,%7}, {%8,%9}, {%0,%1,%2,%3};"
                 : "+f"(c[0]), "+f"(c[1]), "+f"(c[2]), "+f"(c[3])
                 : "r"(a[0]), "r"(a[1]), "r"(a[2]), "r"(a[3]), "r"(b0), "r"(b1));
}

// ---------------------------------------------------------------------------
// Conversion kernels
// ---------------------------------------------------------------------------
struct Ptr3 { const float* p[3]; };

__global__ __launch_bounds__(256)
void split_x_kernel(Ptr3 in) {
    const int z = blockIdx.y;
    const size_t idx = ((size_t)blockIdx.x * blockDim.x + threadIdx.x) * 4;
    const float4 v = *reinterpret_cast<const float4*>(in.p[z] + idx);

    __nv_bfloat16 h0 = __float2bfloat16_rn(v.x);
    __nv_bfloat16 h1 = __float2bfloat16_rn(v.y);
    __nv_bfloat16 h2 = __float2bfloat16_rn(v.z);
    __nv_bfloat16 h3 = __float2bfloat16_rn(v.w);
    __nv_bfloat16 l0 = __float2bfloat16_rn(v.x - __bfloat162float(h0));
    __nv_bfloat16 l1 = __float2bfloat16_rn(v.y - __bfloat162float(h1));
    __nv_bfloat16 l2 = __float2bfloat16_rn(v.z - __bfloat162float(h2));
    __nv_bfloat16 l3 = __float2bfloat16_rn(v.w - __bfloat162float(h3));

    ushort4 hv = make_ushort4(__bfloat16_as_ushort(h0), __bfloat16_as_ushort(h1),
                              __bfloat16_as_ushort(h2), __bfloat16_as_ushort(h3));
    ushort4 lv = make_ushort4(__bfloat16_as_ushort(l0), __bfloat16_as_ushort(l1),
                              __bfloat16_as_ushort(l2), __bfloat16_as_ushort(l3));
    const size_t base = (size_t)z * MROWS * HIDDEN + idx;
    *reinterpret_cast<ushort4*>(g_XHI + base) = hv;
    *reinterpret_cast<ushort4*>(g_XLO + base) = lv;
}

// W[k][n] fp32 -> W^T hi/lo [n][k] bf16 (transpose + split)
__global__ __launch_bounds__(256)
void split_w_kernel(Ptr3 w) {
    __shared__ float t[32][33];
    const int z  = blockIdx.z;
    const int k0 = blockIdx.y * 32;
    const int n0 = blockIdx.x * 32;
    const int tx = threadIdx.x & 31;
    const int ty = threadIdx.x >> 5;
    const float* W = w.p[z];

#pragma unroll
    for (int j = 0; j < 32; j += 8)
        t[ty + j][tx] = W[(size_t)(k0 + ty + j) * HIDDEN + n0 + tx];
    __syncthreads();

    __nv_bfloat16* oh = g_WHI + (size_t)z * HIDDEN * HIDDEN;
    __nv_bfloat16* ol = g_WLO + (size_t)z * HIDDEN * HIDDEN;
#pragma unroll
    for (int j = 0; j < 32; j += 8) {
        float v = t[tx][ty + j];
        __nv_bfloat16 h = __float2bfloat16_rn(v);
        __nv_bfloat16 l = __float2bfloat16_rn(v - __bfloat162float(h));
        oh[(size_t)(n0 + ty + j) * HIDDEN + k0 + tx] = h;
        ol[(size_t)(n0 + ty + j) * HIDDEN + k0 + tx] = l;
    }
}

__global__ __launch_bounds__(256)
void zero_m_kernel() {
    g_M[(size_t)blockIdx.x * 256 + threadIdx.x] = 0.0f;
}

// ---------------------------------------------------------------------------
// Tensor-core (mma.sync bf16, 3-term split) projection GEMM
// Y = X @ W + b;  BM=128, BN=128, BK=32, 8 warps, 3-stage cp.async pipeline.
// ---------------------------------------------------------------------------
#define SSTR      80                     /* padded row stride (bytes) for 32 bf16 */
#define ARR_BYTES (128 * SSTR)           /* 10240 */
#define OFF_AH    0
#define OFF_AL    (ARR_BYTES)
#define OFF_BH    (2 * ARR_BYTES)
#define OFF_BL    (3 * ARR_BYTES)
#define STAGE_B   (4 * ARR_BYTES)        /* 40960 */
#define NSTAGE    3
#define SMEM_DYN  (NSTAGE * STAGE_B)     /* 122880 */
#define KITERS    (HIDDEN / 32)          /* 32 */

struct GemmArgs { const float* Bv[3]; float* Y[3]; };

__device__ __forceinline__ void load_stage(uint32_t sbase,
                                           const __nv_bfloat16* Ah, const __nv_bfloat16* Al,
                                           const __nv_bfloat16* Bh, const __nv_bfloat16* Bl,
                                           int tid) {
    // 4 arrays x 512 chunks of 16B; 256 threads x 2 chunks each per array
#pragma unroll
    for (int j = 0; j < 2; j++) {
        const int c   = tid + j * 256;
        const int row = c >> 2;
        const int cc  = c & 3;
        const uint32_t d = sbase + (uint32_t)row * SSTR + (uint32_t)cc * 16;
        const size_t   s = (size_t)row * HIDDEN + cc * 8;
        cp16(d + OFF_AH, Ah + s);
        cp16(d + OFF_AL, Al + s);
        cp16(d + OFF_BH, Bh + s);
        cp16(d + OFF_BL, Bl + s);
    }
}

__global__ __launch_bounds__(256, 1)
void proj_gemm_mma(GemmArgs args) {
    extern __shared__ char dynsmem[];
    const uint32_t sb0 = smem_u32(dynsmem);

    const int tid   = threadIdx.x;
    const int wid   = tid >> 5;
    const int lane  = tid & 31;
    const int warpM = wid >> 2;         // 0..1  (64 rows each)
    const int warpN = wid & 3;          // 0..3  (32 cols each)
    const int z     = blockIdx.z;
    const int n0    = blockIdx.x * 128;
    const int m0    = blockIdx.y * 128;

    const __nv_bfloat16* Ah = g_XHI + (size_t)z * MROWS * HIDDEN + (size_t)m0 * HIDDEN;
    const __nv_bfloat16* Al = g_XLO + (size_t)z * MROWS * HIDDEN + (size_t)m0 * HIDDEN;
    const __nv_bfloat16* Bh = g_WHI + (size_t)z * HIDDEN * HIDDEN + (size_t)n0 * HIDDEN;
    const __nv_bfloat16* Bl = g_WLO + (size_t)z * HIDDEN * HIDDEN + (size_t)n0 * HIDDEN;

    // Per-lane ldmatrix base offsets
    const int grp = lane >> 3;
    const int rin = lane & 7;
    const uint32_t aBase = (uint32_t)(warpM * 64 + (grp & 1) * 8 + rin) * SSTR + (uint32_t)(grp >> 1) * 16;
    const uint32_t bBase = (uint32_t)(warpN * 32 + (grp >> 1) * 8 + rin) * SSTR + (uint32_t)(grp & 1) * 16;

    float acc[4][4][4];   // [mt][nt][reg]
#pragma unroll
    for (int i = 0; i < 4; i++)
#pragma unroll
        for (int j = 0; j < 4; j++)
#pragma unroll
            for (int r = 0; r < 4; r++) acc[i][j][r] = 0.0f;

    // Prologue: stages 0, 1
    load_stage(sb0,           Ah,      Al,      Bh,      Bl,      tid);
    CP_COMMIT();
    load_stage(sb0 + STAGE_B, Ah + 32, Al + 32, Bh + 32, Bl + 32, tid);
    CP_COMMIT();

    for (int i = 0; i < KITERS; i++) {
        const uint32_t sb = sb0 + (uint32_t)(i % NSTAGE) * STAGE_B;
        CP_WAIT1();
        __syncthreads();

#pragma unroll
        for (int ks = 0; ks < 32; ks += 16) {
            uint32_t aH[4][4], aL[4][4], bH[4][2], bL[4][2];
#pragma unroll
            for (int mt = 0; mt < 4; mt++) {
                const uint32_t ad = sb + aBase + (uint32_t)mt * (16 * SSTR) + ks * 2;
                ldsm4(aH[mt], ad + OFF_AH);
                ldsm4(aL[mt], ad + OFF_AL);
            }
#pragma unroll
            for (int p = 0; p < 2; p++) {
                const uint32_t bd = sb + bBase + (uint32_t)p * (16 * SSTR) + ks * 2;
                uint32_t t[4];
                ldsm4(t, bd + OFF_BH);
                bH[2 * p][0] = t[0]; bH[2 * p][1] = t[1];
                bH[2 * p + 1][0] = t[2]; bH[2 * p + 1][1] = t[3];
                ldsm4(t, bd + OFF_BL);
                bL[2 * p][0] = t[0]; bL[2 * p][1] = t[1];
                bL[2 * p + 1][0] = t[2]; bL[2 * p + 1][1] = t[3];
            }
#pragma unroll
            for (int mt = 0; mt < 4; mt++)
#pragma unroll
                for (int nt = 0; nt < 4; nt++) {
                    mma_bf16(acc[mt][nt], aH[mt], bH[nt][0], bH[nt][1]);
                    mma_bf16(acc[mt][nt], aL[mt], bH[nt][0], bH[nt][1]);
                    mma_bf16(acc[mt][nt], aH[mt], bL[nt][0], bL[nt][1]);
                }
        }

        if (i + 2 < KITERS) {
            const uint32_t sn = sb0 + (uint32_t)((i + 2) % NSTAGE) * STAGE_B;
            const int ko = (i + 2) * 32;
            load_stage(sn, Ah + ko, Al + ko, Bh + ko, Bl + ko, tid);
        }
        CP_COMMIT();
    }

    // Epilogue: bias + store fp32
    const float* Bv = args.Bv[z];
    float* Y = args.Y[z];
    const int rowBase = m0 + warpM * 64 + (lane >> 2);
    const int colBase = n0 + warpN * 32 + (lane & 3) * 2;
#pragma unroll
    for (int mt = 0; mt < 4; mt++) {
#pragma unroll
        for (int nt = 0; nt < 4; nt++) {
            const int col = colBase + nt * 8;
            const float b0 = Bv[col], b1 = Bv[col + 1];
            const int r0 = rowBase + mt * 16;
            float2 v0 = make_float2(acc[mt][nt][0] + b0, acc[mt][nt][1] + b1);
            float2 v1 = make_float2(acc[mt][nt][2] + b0, acc[mt][nt][3] + b1);
            *reinterpret_cast<float2*>(Y + (size_t)r0 * HIDDEN + col)       = v0;
            *reinterpret_cast<float2*>(Y + (size_t)(r0 + 8) * HIDDEN + col) = v1;
        }
    }
}

// ---------------------------------------------------------------------------
// Kernel 2: per (b,h,chunk) partial M_h += K_h^T V_h  (split-8 over S)
// ---------------------------------------------------------------------------
#define KTV_SPLIT 8
#define KTV_CHUNK (SEQ / KTV_SPLIT)   /* 256 */

__global__ __launch_bounds__(256)
void ktv_gemm() {
    const int bh = blockIdx.x;
    const int b  = bh >> 4;
    const int h  = bh & 15;
    const int sbeg = blockIdx.y * KTV_CHUNK;

    const float* Kb = g_K + (size_t)b * SEQ * HIDDEN + h * HEAD_DIM;
    const float* Vb = g_V + (size_t)b * SEQ * HIDDEN + h * HEAD_DIM;

    __shared__ float Ks[64 * 64];
    __shared__ float Vs[64 * 64];

    const int tid = threadIdx.x;
    const int tx  = tid & 15;
    const int ty  = tid >> 4;

    float acc[4][4];
#pragma unroll
    for (int i = 0; i < 4; i++)
#pragma unroll
        for (int j = 0; j < 4; j++) acc[i][j] = 0.0f;

    for (int s0 = sbeg; s0 < sbeg + KTV_CHUNK; s0 += 64) {
#pragma unroll
        for (int t = 0; t < 4; t++) {
            int e   = (tid + t * 256) * 4;
            int row = e >> 6;
            int col = e & 63;
            *reinterpret_cast<float4*>(&Ks[e]) =
                *reinterpret_cast<const float4*>(Kb + (size_t)(s0 + row) * HIDDEN + col);
            *reinterpret_cast<float4*>(&Vs[e]) =
                *reinterpret_cast<const float4*>(Vb + (size_t)(s0 + row) * HIDDEN + col);
        }
        __syncthreads();

#pragma unroll 4
        for (int ss = 0; ss < 64; ss++) {
            float kv[4], vv[4];
            *reinterpret_cast<float4*>(kv) = *reinterpret_cast<const float4*>(&Ks[ss * 64 + ty * 4]);
            *reinterpret_cast<float4*>(vv) = *reinterpret_cast<const float4*>(&Vs[ss * 64 + tx * 4]);
#pragma unroll
            for (int i = 0; i < 4; i++)
#pragma unroll
                for (int j = 0; j < 4; j++)
                    acc[i][j] = fmaf(kv[i], vv[j], acc[i][j]);
        }
        __syncthreads();
    }

    float* Mh = g_M + (size_t)bh * HEAD_DIM * HEAD_DIM;
#pragma unroll
    for (int i = 0; i < 4; i++)
#pragma unroll
        for (int j = 0; j < 4; j++)
            atomicAdd(&Mh[(ty * 4 + i) * 64 + tx * 4 + j], acc[i][j]);
}

// ---------------------------------------------------------------------------
// Kernel 3: out_h = scale * Q_h @ M_h
// ---------------------------------------------------------------------------
__global__ __launch_bounds__(256)
void out_gemm(float* __restrict__ out) {
    const int bh = blockIdx.y;
    const int b  = bh >> 4;
    const int h  = bh & 15;
    const int s0 = blockIdx.x * 64;
    const float scale = 0.125f;

    const float* Qb = g_Q + (size_t)b * SEQ * HIDDEN + h * HEAD_DIM;
    const float* Mh = g_M + (size_t)bh * HEAD_DIM * HEAD_DIM;

    __shared__ float Qs[64 * 64];
    __shared__ float Ms[64 * 64];

    const int tid = threadIdx.x;
    const int tx  = tid & 15;
    const int ty  = tid >> 4;

#pragma unroll
    for (int t = 0; t < 4; t++) {
        int e   = (tid + t * 256) * 4;
        int row = e >> 6;
        int col = e & 63;
        *reinterpret_cast<float4*>(&Qs[e]) =
            *reinterpret_cast<const float4*>(Qb + (size_t)(s0 + row) * HIDDEN + col);
        *reinterpret_cast<float4*>(&Ms[e]) = *reinterpret_cast<const float4*>(&Mh[e]);
    }
    __syncthreads();

    float acc[4][4];
#pragma unroll
    for (int i = 0; i < 4; i++)
#pragma unroll
        for (int j = 0; j < 4; j++) acc[i][j] = 0.0f;

#pragma unroll 4
    for (int k = 0; k < 64; k++) {
        float qv[4], mv[4];
#pragma unroll
        for (int i = 0; i < 4; i++) qv[i] = Qs[(ty * 4 + i) * 64 + k];
        *reinterpret_cast<float4*>(mv) = *reinterpret_cast<const float4*>(&Ms[k * 64 + tx * 4]);
#pragma unroll
        for (int i = 0; i < 4; i++)
#pragma unroll
            for (int j = 0; j < 4; j++)
                acc[i][j] = fmaf(qv[i], mv[j], acc[i][j]);
    }

#pragma unroll
    for (int i = 0; i < 4; i++) {
        float4 v = make_float4(scale * acc[i][0], scale * acc[i][1],
                               scale * acc[i][2], scale * acc[i][3]);
        *reinterpret_cast<float4*>(out + (size_t)(b * SEQ + s0 + ty * 4 + i) * HIDDEN
                                   + h * HEAD_DIM + tx * 4) = v;
    }
}

// ---------------------------------------------------------------------------
extern "C" void kernel_launch(void* const* d_in, const int* in_sizes, int n_in,
                              void* d_out, int out_size) {
    (void)in_sizes; (void)n_in; (void)out_size;
    const float* query = (const float*)d_in[0];
    const float* key   = (const float*)d_in[1];
    const float* value = (const float*)d_in[2];
    const float* q_w   = (const float*)d_in[3];
    const float* q_b   = (const float*)d_in[4];
    const float* k_w   = (const float*)d_in[5];
    const float* k_b   = (const float*)d_in[6];
    const float* v_w   = (const float*)d_in[7];
    const float* v_b   = (const float*)d_in[8];
    float* out = (float*)d_out;

    void *qp, *kp, *vp;
    cudaGetSymbolAddress(&qp, g_Q);
    cudaGetSymbolAddress(&kp, g_K);
    cudaGetSymbolAddress(&vp, g_V);

    cudaFuncSetAttribute(proj_gemm_mma, cudaFuncAttributeMaxDynamicSharedMemorySize, SMEM_DYN);

    Ptr3 xin; xin.p[0] = query; xin.p[1] = key; xin.p[2] = value;
    Ptr3 win; win.p[0] = q_w;   win.p[1] = k_w; win.p[2] = v_w;

    // 1. fp32 -> bf16 hi/lo splits
    dim3 xgrid((unsigned)((size_t)MROWS * HIDDEN / 4 / 256), 3);
    split_x_kernel<<<xgrid, 256>>>(xin);
    split_w_kernel<<<dim3(HIDDEN / 32, HIDDEN / 32, 3), 256>>>(win);
    zero_m_kernel<<<(BATCH * HEADS * HEAD_DIM * HEAD_DIM) / 256, 256>>>();

    // 2. Tensor-core projections (mma.sync bf16, 3 terms)
    GemmArgs ga;
    ga.Bv[0] = q_b; ga.Bv[1] = k_b; ga.Bv[2] = v_b;
    ga.Y[0] = (float*)qp; ga.Y[1] = (float*)kp; ga.Y[2] = (float*)vp;
    proj_gemm_mma<<<dim3(HIDDEN / 128, MROWS / 128, 3), 256, SMEM_DYN>>>(ga);

    // 3. Small batched GEMMs
    ktv_gemm<<<dim3(BATCH * HEADS, KTV_SPLIT), 256>>>();
    out_gemm<<<dim3(SEQ / 64, BATCH * HEADS), 256>>>(out);
}

// round 5
// speedup vs baseline: 2.5488x; 1.2143x over previous
#include <cuda_runtime.h>
#include <cuda_fp16.h>
#include <cstdint>

#define HIDDEN   1024
#define HEADS    16
#define HEAD_DIM 64
#define BATCH    4
#define SEQ      2048
#define MROWS    (BATCH * SEQ)   /* 8192 */

// ---------------------------------------------------------------------------
// Device-global scratch
// ---------------------------------------------------------------------------
__device__ float g_Q[MROWS * HIDDEN];
__device__ float g_K[MROWS * HIDDEN];
__device__ float g_V[MROWS * HIDDEN];
__device__ float g_M[BATCH * HEADS * HEAD_DIM * HEAD_DIM];

__device__ __half g_XHI[3ull * MROWS * HIDDEN];   // X hi ([M][K]) fp16
__device__ __half g_XLO[3ull * MROWS * HIDDEN];   // X lo
__device__ __half g_WHI[3ull * HIDDEN * HIDDEN];  // W^T hi ([N][K]) fp16 (no lo)

// ---------------------------------------------------------------------------
// Helpers (target-portable sm_80-class PTX only)
// ---------------------------------------------------------------------------
__device__ __forceinline__ uint32_t smem_u32(const void* p) {
    uint32_t a;
    asm("{ .reg .u64 t; cvta.to.shared.u64 t, %1; cvt.u32.u64 %0, t; }" : "=r"(a) : "l"(p));
    return a;
}
__device__ __forceinline__ void cp16(uint32_t dst, const void* src) {
    asm volatile("cp.async.cg.shared.global [%0], [%1], 16;" :: "r"(dst), "l"(src));
}
#define CP_COMMIT() asm volatile("cp.async.commit_group;" ::: "memory")
#define CP_WAIT1()  asm volatile("cp.async.wait_group 1;"  ::: "memory")

__device__ __forceinline__ void ldsm4(uint32_t (&r)[4], uint32_t addr) {
    asm volatile("ldmatrix.sync.aligned.m8n8.x4.shared.b16 {%0,%1,%2,%3}, [%4];"
                 : "=r"(r[0]), "=r"(r[1]), "=r"(r[2]), "=r"(r[3]) : "r"(addr));
}
__device__ __forceinline__ void mma_fp16(float (&c)[4], const uint32_t (&a)[4],
                                         uint32_t b0, uint32_t b1) {
    asm volatile("mma.sync.aligned.m16n8k16.row.col.f32.f16.f16.f32 "
                 "{%0,%1,%2,%3}, {%4,%5,%6,%7}, {%8,%9}, {%0,%1,%2,%3};"
                 : "+f"(c[0]), "+f"(c[1]), "+f"(c[2]), "+f"(c[3])
                 : "r"(a[0]), "r"(a[1]), "r"(a[2]), "r"(a[3]), "r"(b0), "r"(b1));
}

// ---------------------------------------------------------------------------
// Conversion kernels
// ---------------------------------------------------------------------------
struct Ptr3 { const float* p[3]; };

__global__ __launch_bounds__(256)
void split_x_kernel(Ptr3 in) {
    const int z = blockIdx.y;
    const size_t idx = ((size_t)blockIdx.x * blockDim.x + threadIdx.x) * 4;
    const float4 v = *reinterpret_cast<const float4*>(in.p[z] + idx);

    __half h0 = __float2half_rn(v.x);
    __half h1 = __float2half_rn(v.y);
    __half h2 = __float2half_rn(v.z);
    __half h3 = __float2half_rn(v.w);
    __half l0 = __float2half_rn(v.x - __half2float(h0));
    __half l1 = __float2half_rn(v.y - __half2float(h1));
    __half l2 = __float2half_rn(v.z - __half2float(h2));
    __half l3 = __float2half_rn(v.w - __half2float(h3));

    ushort4 hv = make_ushort4(__half_as_ushort(h0), __half_as_ushort(h1),
                              __half_as_ushort(h2), __half_as_ushort(h3));
    ushort4 lv = make_ushort4(__half_as_ushort(l0), __half_as_ushort(l1),
                              __half_as_ushort(l2), __half_as_ushort(l3));
    const size_t base = (size_t)z * MROWS * HIDDEN + idx;
    *reinterpret_cast<ushort4*>(g_XHI + base) = hv;
    *reinterpret_cast<ushort4*>(g_XLO + base) = lv;
}

// W[k][n] fp32 -> W^T hi [n][k] fp16 (transpose, hi only)
__global__ __launch_bounds__(256)
void split_w_kernel(Ptr3 w) {
    __shared__ float t[32][33];
    const int z  = blockIdx.z;
    const int k0 = blockIdx.y * 32;
    const int n0 = blockIdx.x * 32;
    const int tx = threadIdx.x & 31;
    const int ty = threadIdx.x >> 5;
    const float* W = w.p[z];

#pragma unroll
    for (int j = 0; j < 32; j += 8)
        t[ty + j][tx] = W[(size_t)(k0 + ty + j) * HIDDEN + n0 + tx];
    __syncthreads();

    __half* oh = g_WHI + (size_t)z * HIDDEN * HIDDEN;
#pragma unroll
    for (int j = 0; j < 32; j += 8)
        oh[(size_t)(n0 + ty + j) * HIDDEN + k0 + tx] = __float2half_rn(t[tx][ty + j]);
}

__global__ __launch_bounds__(256)
void zero_m_kernel() {
    g_M[(size_t)blockIdx.x * 256 + threadIdx.x] = 0.0f;
}

// ---------------------------------------------------------------------------
// fp16 2-term (A hi/lo, B hi) projection GEMM on mma.sync
// BM=128, BN=256, BK=32, 8 warps (warp tile 64x64), 3-stage cp.async pipeline.
// ---------------------------------------------------------------------------
#define SSTR      80                     /* padded row stride (bytes) for 32 fp16 */
#define A_BYTES   (128 * SSTR)           /* 10240 */
#define B_BYTES   (256 * SSTR)           /* 20480 */
#define OFF_AH    0
#define OFF_AL    (A_BYTES)
#define OFF_BH    (2 * A_BYTES)
#define STAGE_B   (2 * A_BYTES + B_BYTES)  /* 40960 */
#define NSTAGE    3
#define SMEM_DYN  (NSTAGE * STAGE_B)       /* 122880 */
#define KITERS    (HIDDEN / 32)            /* 32 */

struct GemmArgs { const float* Bv[3]; float* Y[3]; };

__device__ __forceinline__ void load_stage(uint32_t sbase,
                                           const __half* Ah, const __half* Al,
                                           const __half* Bh, int tid) {
    // A arrays: 512 chunks of 16B each -> 2 per thread per array
#pragma unroll
    for (int j = 0; j < 2; j++) {
        const int c   = tid + j * 256;
        const int row = c >> 2;
        const int cc  = c & 3;
        const uint32_t d = sbase + (uint32_t)row * SSTR + (uint32_t)cc * 16;
        const size_t   s = (size_t)row * HIDDEN + cc * 8;
        cp16(d + OFF_AH, Ah + s);
        cp16(d + OFF_AL, Al + s);
    }
    // B array: 1024 chunks -> 4 per thread
#pragma unroll
    for (int j = 0; j < 4; j++) {
        const int c   = tid + j * 256;
        const int row = c >> 2;
        const int cc  = c & 3;
        const uint32_t d = sbase + (uint32_t)row * SSTR + (uint32_t)cc * 16;
        cp16(d + OFF_BH, Bh + (size_t)row * HIDDEN + cc * 8);
    }
}

__global__ __launch_bounds__(256, 1)
void proj_gemm_mma(GemmArgs args) {
    extern __shared__ char dynsmem[];
    const uint32_t sb0 = smem_u32(dynsmem);

    const int tid   = threadIdx.x;
    const int wid   = tid >> 5;
    const int lane  = tid & 31;
    const int warpM = wid >> 2;         // 0..1  (64 rows each)
    const int warpN = wid & 3;          // 0..3  (64 cols each)
    const int z     = blockIdx.z;
    const int n0    = blockIdx.x * 256;
    const int m0    = blockIdx.y * 128;

    const __half* Ah = g_XHI + (size_t)z * MROWS * HIDDEN + (size_t)m0 * HIDDEN;
    const __half* Al = g_XLO + (size_t)z * MROWS * HIDDEN + (size_t)m0 * HIDDEN;
    const __half* Bh = g_WHI + (size_t)z * HIDDEN * HIDDEN + (size_t)n0 * HIDDEN;

    // Per-lane ldmatrix base offsets
    const int grp = lane >> 3;
    const int rin = lane & 7;
    const uint32_t aBase = (uint32_t)(warpM * 64 + (grp & 1) * 8 + rin) * SSTR + (uint32_t)(grp >> 1) * 16;
    const uint32_t bBase = (uint32_t)(warpN * 64 + (grp >> 1) * 8 + rin) * SSTR + (uint32_t)(grp & 1) * 16;

    float acc[4][8][4];   // [mt][nt][reg] : 64 rows x 64 cols per warp
#pragma unroll
    for (int i = 0; i < 4; i++)
#pragma unroll
        for (int j = 0; j < 8; j++)
#pragma unroll
            for (int r = 0; r < 4; r++) acc[i][j][r] = 0.0f;

    // Prologue: stages 0, 1
    load_stage(sb0,           Ah,      Al,      Bh,      tid);
    CP_COMMIT();
    load_stage(sb0 + STAGE_B, Ah + 32, Al + 32, Bh + 32, tid);
    CP_COMMIT();

    for (int i = 0; i < KITERS; i++) {
        const uint32_t sb = sb0 + (uint32_t)(i % NSTAGE) * STAGE_B;
        CP_WAIT1();
        __syncthreads();

        // Issue next stage loads FIRST so cp.async overlaps the MMA work below.
        if (i + 2 < KITERS) {
            const uint32_t sn = sb0 + (uint32_t)((i + 2) % NSTAGE) * STAGE_B;
            const int ko = (i + 2) * 32;
            load_stage(sn, Ah + ko, Al + ko, Bh + ko, tid);
        }
        CP_COMMIT();

#pragma unroll
        for (int ks = 0; ks < 32; ks += 16) {
            uint32_t aH[4][4], aL[4][4], bH[8][2];
#pragma unroll
            for (int mt = 0; mt < 4; mt++) {
                const uint32_t ad = sb + aBase + (uint32_t)mt * (16 * SSTR) + ks * 2;
                ldsm4(aH[mt], ad + OFF_AH);
                ldsm4(aL[mt], ad + OFF_AL);
            }
#pragma unroll
            for (int p = 0; p < 4; p++) {
                const uint32_t bd = sb + OFF_BH + bBase + (uint32_t)p * (16 * SSTR) + ks * 2;
                uint32_t t[4];
                ldsm4(t, bd);
                bH[2 * p][0] = t[0]; bH[2 * p][1] = t[1];
                bH[2 * p + 1][0] = t[2]; bH[2 * p + 1][1] = t[3];
            }
#pragma unroll
            for (int mt = 0; mt < 4; mt++)
#pragma unroll
                for (int nt = 0; nt < 8; nt++) {
                    mma_fp16(acc[mt][nt], aH[mt], bH[nt][0], bH[nt][1]);
                    mma_fp16(acc[mt][nt], aL[mt], bH[nt][0], bH[nt][1]);
                }
        }
    }

    // Epilogue: bias + store fp32
    const float* Bv = args.Bv[z];
    float* Y = args.Y[z];
    const int rowBase = m0 + warpM * 64 + (lane >> 2);
    const int colBase = n0 + warpN * 64 + (lane & 3) * 2;
#pragma unroll
    for (int mt = 0; mt < 4; mt++) {
#pragma unroll
        for (int nt = 0; nt < 8; nt++) {
            const int col = colBase + nt * 8;
            const float b0 = Bv[col], b1 = Bv[col + 1];
            const int r0 = rowBase + mt * 16;
            float2 v0 = make_float2(acc[mt][nt][0] + b0, acc[mt][nt][1] + b1);
            float2 v1 = make_float2(acc[mt][nt][2] + b0, acc[mt][nt][3] + b1);
            *reinterpret_cast<float2*>(Y + (size_t)r0 * HIDDEN + col)       = v0;
            *reinterpret_cast<float2*>(Y + (size_t)(r0 + 8) * HIDDEN + col) = v1;
        }
    }
}

// ---------------------------------------------------------------------------
// Kernel 2: per (b,h,chunk) partial M_h += K_h^T V_h  (split-8 over S)
// ---------------------------------------------------------------------------
#define KTV_SPLIT 8
#define KTV_CHUNK (SEQ / KTV_SPLIT)   /* 256 */

__global__ __launch_bounds__(256)
void ktv_gemm() {
    const int bh = blockIdx.x;
    const int b  = bh >> 4;
    const int h  = bh & 15;
    const int sbeg = blockIdx.y * KTV_CHUNK;

    const float* Kb = g_K + (size_t)b * SEQ * HIDDEN + h * HEAD_DIM;
    const float* Vb = g_V + (size_t)b * SEQ * HIDDEN + h * HEAD_DIM;

    __shared__ float Ks[64 * 64];
    __shared__ float Vs[64 * 64];

    const int tid = threadIdx.x;
    const int tx  = tid & 15;
    const int ty  = tid >> 4;

    float acc[4][4];
#pragma unroll
    for (int i = 0; i < 4; i++)
#pragma unroll
        for (int j = 0; j < 4; j++) acc[i][j] = 0.0f;

    for (int s0 = sbeg; s0 < sbeg + KTV_CHUNK; s0 += 64) {
#pragma unroll
        for (int t = 0; t < 4; t++) {
            int e   = (tid + t * 256) * 4;
            int row = e >> 6;
            int col = e & 63;
            *reinterpret_cast<float4*>(&Ks[e]) =
                *reinterpret_cast<const float4*>(Kb + (size_t)(s0 + row) * HIDDEN + col);
            *reinterpret_cast<float4*>(&Vs[e]) =
                *reinterpret_cast<const float4*>(Vb + (size_t)(s0 + row) * HIDDEN + col);
        }
        __syncthreads();

#pragma unroll 4
        for (int ss = 0; ss < 64; ss++) {
            float kv[4], vv[4];
            *reinterpret_cast<float4*>(kv) = *reinterpret_cast<const float4*>(&Ks[ss * 64 + ty * 4]);
            *reinterpret_cast<float4*>(vv) = *reinterpret_cast<const float4*>(&Vs[ss * 64 + tx * 4]);
#pragma unroll
            for (int i = 0; i < 4; i++)
#pragma unroll
                for (int j = 0; j < 4; j++)
                    acc[i][j] = fmaf(kv[i], vv[j], acc[i][j]);
        }
        __syncthreads();
    }

    float* Mh = g_M + (size_t)bh * HEAD_DIM * HEAD_DIM;
#pragma unroll
    for (int i = 0; i < 4; i++)
#pragma unroll
        for (int j = 0; j < 4; j++)
            atomicAdd(&Mh[(ty * 4 + i) * 64 + tx * 4 + j], acc[i][j]);
}

// ---------------------------------------------------------------------------
// Kernel 3: out_h = scale * Q_h @ M_h
// ---------------------------------------------------------------------------
__global__ __launch_bounds__(256)
void out_gemm(float* __restrict__ out) {
    const int bh = blockIdx.y;
    const int b  = bh >> 4;
    const int h  = bh & 15;
    const int s0 = blockIdx.x * 64;
    const float scale = 0.125f;

    const float* Qb = g_Q + (size_t)b * SEQ * HIDDEN + h * HEAD_DIM;
    const float* Mh = g_M + (size_t)bh * HEAD_DIM * HEAD_DIM;

    __shared__ float Qs[64 * 64];
    __shared__ float Ms[64 * 64];

    const int tid = threadIdx.x;
    const int tx  = tid & 15;
    const int ty  = tid >> 4;

#pragma unroll
    for (int t = 0; t < 4; t++) {
        int e   = (tid + t * 256) * 4;
        int row = e >> 6;
        int col = e & 63;
        *reinterpret_cast<float4*>(&Qs[e]) =
            *reinterpret_cast<const float4*>(Qb + (size_t)(s0 + row) * HIDDEN + col);
        *reinterpret_cast<float4*>(&Ms[e]) = *reinterpret_cast<const float4*>(&Mh[e]);
    }
    __syncthreads();

    float acc[4][4];
#pragma unroll
    for (int i = 0; i < 4; i++)
#pragma unroll
        for (int j = 0; j < 4; j++) acc[i][j] = 0.0f;

#pragma unroll 4
    for (int k = 0; k < 64; k++) {
        float qv[4], mv[4];
#pragma unroll
        for (int i = 0; i < 4; i++) qv[i] = Qs[(ty * 4 + i) * 64 + k];
        *reinterpret_cast<float4*>(mv) = *reinterpret_cast<const float4*>(&Ms[k * 64 + tx * 4]);
#pragma unroll
        for (int i = 0; i < 4; i++)
#pragma unroll
            for (int j = 0; j < 4; j++)
                acc[i][j] = fmaf(qv[i], mv[j], acc[i][j]);
    }

#pragma unroll
    for (int i = 0; i < 4; i++) {
        float4 v = make_float4(scale * acc[i][0], scale * acc[i][1],
                               scale * acc[i][2], scale * acc[i][3]);
        *reinterpret_cast<float4*>(out + (size_t)(b * SEQ + s0 + ty * 4 + i) * HIDDEN
                                   + h * HEAD_DIM + tx * 4) = v;
    }
}

// ---------------------------------------------------------------------------
extern "C" void kernel_launch(void* const* d_in, const int* in_sizes, int n_in,
                              void* d_out, int out_size) {
    (void)in_sizes; (void)n_in; (void)out_size;
    const float* query = (const float*)d_in[0];
    const float* key   = (const float*)d_in[1];
    const float* value = (const float*)d_in[2];
    const float* q_w   = (const float*)d_in[3];
    const float* q_b   = (const float*)d_in[4];
    const float* k_w   = (const float*)d_in[5];
    const float* k_b   = (const float*)d_in[6];
    const float* v_w   = (const float*)d_in[7];
    const float* v_b   = (const float*)d_in[8];
    float* out = (float*)d_out;

    void *qp, *kp, *vp;
    cudaGetSymbolAddress(&qp, g_Q);
    cudaGetSymbolAddress(&kp, g_K);
    cudaGetSymbolAddress(&vp, g_V);

    cudaFuncSetAttribute(proj_gemm_mma, cudaFuncAttributeMaxDynamicSharedMemorySize, SMEM_DYN);

    Ptr3 xin; xin.p[0] = query; xin.p[1] = key; xin.p[2] = value;
    Ptr3 win; win.p[0] = q_w;   win.p[1] = k_w; win.p[2] = v_w;

    // 1. fp32 -> fp16 splits (A: hi+lo, B: hi only)
    dim3 xgrid((unsigned)((size_t)MROWS * HIDDEN / 4 / 256), 3);
    split_x_kernel<<<xgrid, 256>>>(xin);
    split_w_kernel<<<dim3(HIDDEN / 32, HIDDEN / 32, 3), 256>>>(win);
    zero_m_kernel<<<(BATCH * HEADS * HEAD_DIM * HEAD_DIM) / 256, 256>>>();

    // 2. Tensor-core projections (fp16 mma, 2 terms)
    GemmArgs ga;
    ga.Bv[0] = q_b; ga.Bv[1] = k_b; ga.Bv[2] = v_b;
    ga.Y[0] = (float*)qp; ga.Y[1] = (float*)kp; ga.Y[2] = (float*)vp;
    proj_gemm_mma<<<dim3(HIDDEN / 256, MROWS / 128, 3), 256, SMEM_DYN>>>(ga);

    // 3. Small batched GEMMs
    ktv_gemm<<<dim3(BATCH * HEADS, KTV_SPLIT), 256>>>();
    out_gemm<<<dim3(SEQ / 64, BATCH * HEADS), 256>>>(out);
}

// round 6
// speedup vs baseline: 2.8001x; 1.0986x over previous
#include <cuda_runtime.h>
#include <cuda_fp16.h>
#include <cstdint>

#define HIDDEN   1024
#define HEADS    16
#define HEAD_DIM 64
#define BATCH    4
#define SEQ      2048
#define MROWS    (BATCH * SEQ)   /* 8192 */

// ---------------------------------------------------------------------------
// Device-global scratch
// ---------------------------------------------------------------------------
__device__ float g_Q[MROWS * HIDDEN];
__device__ float g_K[MROWS * HIDDEN];
__device__ float g_V[MROWS * HIDDEN];
__device__ float g_M[BATCH * HEADS * HEAD_DIM * HEAD_DIM];

__device__ __half g_XHI[3ull * MROWS * HIDDEN];   // X hi ([M][K]) fp16
__device__ __half g_XLO[3ull * MROWS * HIDDEN];   // X lo
__device__ __half g_WHI[3ull * HIDDEN * HIDDEN];  // W^T hi ([N][K]) fp16

// ---------------------------------------------------------------------------
// Helpers (target-portable sm_80-class PTX only)
// ---------------------------------------------------------------------------
__device__ __forceinline__ uint32_t smem_u32(const void* p) {
    uint32_t a;
    asm("{ .reg .u64 t; cvta.to.shared.u64 t, %1; cvt.u32.u64 %0, t; }" : "=r"(a) : "l"(p));
    return a;
}
__device__ __forceinline__ void cp16(uint32_t dst, const void* src) {
    asm volatile("cp.async.cg.shared.global [%0], [%1], 16;" :: "r"(dst), "l"(src));
}
#define CP_COMMIT() asm volatile("cp.async.commit_group;" ::: "memory")
#define CP_WAIT1()  asm volatile("cp.async.wait_group 1;"  ::: "memory")

__device__ __forceinline__ void ldsm4(uint32_t (&r)[4], uint32_t addr) {
    asm volatile("ldmatrix.sync.aligned.m8n8.x4.shared.b16 {%0,%1,%2,%3}, [%4];"
                 : "=r"(r[0]), "=r"(r[1]), "=r"(r[2]), "=r"(r[3]) : "r"(addr));
}
__device__ __forceinline__ void mma_fp16(float (&c)[4], const uint32_t (&a)[4],
                                         uint32_t b0, uint32_t b1) {
    asm volatile("mma.sync.aligned.m16n8k16.row.col.f32.f16.f16.f32 "
                 "{%0,%1,%2,%3}, {%4,%5,%6,%7}, {%8,%9}, {%0,%1,%2,%3};"
                 : "+f"(c[0]), "+f"(c[1]), "+f"(c[2]), "+f"(c[3])
                 : "r"(a[0]), "r"(a[1]), "r"(a[2]), "r"(a[3]), "r"(b0), "r"(b1));
}

// ---------------------------------------------------------------------------
// Conversion kernels
// ---------------------------------------------------------------------------
struct Ptr3 { const float* p[3]; };

__global__ __launch_bounds__(256)
void split_x_kernel(Ptr3 in) {
    const int z = blockIdx.y;
    const size_t idx = ((size_t)blockIdx.x * blockDim.x + threadIdx.x) * 4;
    const float4 v = *reinterpret_cast<const float4*>(in.p[z] + idx);

    __half h0 = __float2half_rn(v.x);
    __half h1 = __float2half_rn(v.y);
    __half h2 = __float2half_rn(v.z);
    __half h3 = __float2half_rn(v.w);
    __half l0 = __float2half_rn(v.x - __half2float(h0));
    __half l1 = __float2half_rn(v.y - __half2float(h1));
    __half l2 = __float2half_rn(v.z - __half2float(h2));
    __half l3 = __float2half_rn(v.w - __half2float(h3));

    ushort4 hv = make_ushort4(__half_as_ushort(h0), __half_as_ushort(h1),
                              __half_as_ushort(h2), __half_as_ushort(h3));
    ushort4 lv = make_ushort4(__half_as_ushort(l0), __half_as_ushort(l1),
                              __half_as_ushort(l2), __half_as_ushort(l3));
    const size_t base = (size_t)z * MROWS * HIDDEN + idx;
    *reinterpret_cast<ushort4*>(g_XHI + base) = hv;
    *reinterpret_cast<ushort4*>(g_XLO + base) = lv;
}

// W[k][n] fp32 -> W^T hi [n][k] fp16 (transpose, hi only)
__global__ __launch_bounds__(256)
void split_w_kernel(Ptr3 w) {
    __shared__ float t[32][33];
    const int z  = blockIdx.z;
    const int k0 = blockIdx.y * 32;
    const int n0 = blockIdx.x * 32;
    const int tx = threadIdx.x & 31;
    const int ty = threadIdx.x >> 5;
    const float* W = w.p[z];

#pragma unroll
    for (int j = 0; j < 32; j += 8)
        t[ty + j][tx] = W[(size_t)(k0 + ty + j) * HIDDEN + n0 + tx];
    __syncthreads();

    __half* oh = g_WHI + (size_t)z * HIDDEN * HIDDEN;
#pragma unroll
    for (int j = 0; j < 32; j += 8)
        oh[(size_t)(n0 + ty + j) * HIDDEN + k0 + tx] = __float2half_rn(t[tx][ty + j]);
}

__global__ __launch_bounds__(256)
void zero_m_kernel() {
    g_M[(size_t)blockIdx.x * 256 + threadIdx.x] = 0.0f;
}

// ---------------------------------------------------------------------------
// fp16 2-term (A hi/lo, B hi) projection GEMM on mma.sync
// BM=128, BN=256, BK=64, 8 warps (warp tile 64x64), 2-stage double buffer.
// ---------------------------------------------------------------------------
#define SSTR      144                    /* 64 fp16 = 128B + 16B pad: stride≡4 words mod 32 */
#define A_BYTES   (128 * SSTR)           /* 18432 */
#define OFF_AH    0
#define OFF_AL    (A_BYTES)
#define OFF_BH    (2 * A_BYTES)          /* 36864 */
#define STAGE_B   (2 * A_BYTES + 256 * SSTR)  /* 73728 */
#define NSTAGE    2
#define SMEM_DYN  (NSTAGE * STAGE_B)     /* 147456 */
#define KITERS    (HIDDEN / 64)          /* 16 */

struct GemmArgs { const float* Bv[3]; float* Y[3]; };

__device__ __forceinline__ void load_stage(uint32_t sbase,
                                           const __half* Ah, const __half* Al,
                                           const __half* Bh, int tid) {
    // A hi/lo: 128 rows x 8 chunks of 16B -> 1024 chunks each -> 4/thread/array
#pragma unroll
    for (int j = 0; j < 4; j++) {
        const int c   = tid + j * 256;
        const int row = c >> 3;
        const int cc  = c & 7;
        const uint32_t d = sbase + (uint32_t)row * SSTR + (uint32_t)cc * 16;
        const size_t   s = (size_t)row * HIDDEN + cc * 8;
        cp16(d + OFF_AH, Ah + s);
        cp16(d + OFF_AL, Al + s);
    }
    // B: 256 rows x 8 chunks -> 2048 chunks -> 8/thread
#pragma unroll
    for (int j = 0; j < 8; j++) {
        const int c   = tid + j * 256;
        const int row = c >> 3;
        const int cc  = c & 7;
        const uint32_t d = sbase + OFF_BH + (uint32_t)row * SSTR + (uint32_t)cc * 16;
        cp16(d, Bh + (size_t)row * HIDDEN + cc * 8);
    }
}

__global__ __launch_bounds__(256, 1)
void proj_gemm_mma(GemmArgs args) {
    extern __shared__ char dynsmem[];
    const uint32_t sb0 = smem_u32(dynsmem);

    const int tid   = threadIdx.x;
    const int wid   = tid >> 5;
    const int lane  = tid & 31;
    const int warpM = wid >> 2;         // 0..1  (64 rows each)
    const int warpN = wid & 3;          // 0..3  (64 cols each)
    const int z     = blockIdx.z;
    const int n0    = blockIdx.x * 256;
    const int m0    = blockIdx.y * 128;

    const __half* Ah = g_XHI + (size_t)z * MROWS * HIDDEN + (size_t)m0 * HIDDEN;
    const __half* Al = g_XLO + (size_t)z * MROWS * HIDDEN + (size_t)m0 * HIDDEN;
    const __half* Bh = g_WHI + (size_t)z * HIDDEN * HIDDEN + (size_t)n0 * HIDDEN;

    // Per-lane ldmatrix base offsets
    const int grp = lane >> 3;
    const int rin = lane & 7;
    const uint32_t aBase = (uint32_t)(warpM * 64 + (grp & 1) * 8 + rin) * SSTR + (uint32_t)(grp >> 1) * 16;
    const uint32_t bBase = (uint32_t)(warpN * 64 + (grp >> 1) * 8 + rin) * SSTR + (uint32_t)(grp & 1) * 16;

    float acc[4][8][4];   // [mt][nt][reg] : 64 rows x 64 cols per warp
#pragma unroll
    for (int i = 0; i < 4; i++)
#pragma unroll
        for (int j = 0; j < 8; j++)
#pragma unroll
            for (int r = 0; r < 4; r++) acc[i][j][r] = 0.0f;

    // Prologue: stage 0
    load_stage(sb0, Ah, Al, Bh, tid);
    CP_COMMIT();

    for (int i = 0; i < KITERS; i++) {
        const uint32_t sb = sb0 + (uint32_t)(i & 1) * STAGE_B;

        // Guard: all warps done reading the buffer we're about to overwrite
        if (i > 0) __syncthreads();
        if (i + 1 < KITERS) {
            const int ko = (i + 1) * 64;
            load_stage(sb0 + (uint32_t)((i + 1) & 1) * STAGE_B, Ah + ko, Al + ko, Bh + ko, tid);
        }
        CP_COMMIT();           // (empty group on last iters keeps wait invariant)
        CP_WAIT1();            // stage i's group complete
        __syncthreads();

#pragma unroll
        for (int ks = 0; ks < 4; ks++) {
            const uint32_t ksB = (uint32_t)ks * 32;
            uint32_t aH[4][4], aL[4][4], bH[8][2];
#pragma unroll
            for (int mt = 0; mt < 4; mt++) {
                const uint32_t ad = sb + aBase + (uint32_t)mt * (16 * SSTR) + ksB;
                ldsm4(aH[mt], ad + OFF_AH);
                ldsm4(aL[mt], ad + OFF_AL);
            }
#pragma unroll
            for (int p = 0; p < 4; p++) {
                const uint32_t bd = sb + OFF_BH + bBase + (uint32_t)p * (16 * SSTR) + ksB;
                uint32_t t[4];
                ldsm4(t, bd);
                bH[2 * p][0] = t[0]; bH[2 * p][1] = t[1];
                bH[2 * p + 1][0] = t[2]; bH[2 * p + 1][1] = t[3];
            }
#pragma unroll
            for (int mt = 0; mt < 4; mt++)
#pragma unroll
                for (int nt = 0; nt < 8; nt++) {
                    mma_fp16(acc[mt][nt], aH[mt], bH[nt][0], bH[nt][1]);
                    mma_fp16(acc[mt][nt], aL[mt], bH[nt][0], bH[nt][1]);
                }
        }
    }

    // Epilogue: bias + store fp32
    const float* Bv = args.Bv[z];
    float* Y = args.Y[z];
    const int rowBase = m0 + warpM * 64 + (lane >> 2);
    const int colBase = n0 + warpN * 64 + (lane & 3) * 2;
#pragma unroll
    for (int mt = 0; mt < 4; mt++) {
#pragma unroll
        for (int nt = 0; nt < 8; nt++) {
            const int col = colBase + nt * 8;
            const float b0 = Bv[col], b1 = Bv[col + 1];
            const int r0 = rowBase + mt * 16;
            float2 v0 = make_float2(acc[mt][nt][0] + b0, acc[mt][nt][1] + b1);
            float2 v1 = make_float2(acc[mt][nt][2] + b0, acc[mt][nt][3] + b1);
            *reinterpret_cast<float2*>(Y + (size_t)r0 * HIDDEN + col)       = v0;
            *reinterpret_cast<float2*>(Y + (size_t)(r0 + 8) * HIDDEN + col) = v1;
        }
    }
}

// ---------------------------------------------------------------------------
// Kernel 2: per (b,h,chunk) partial M_h += K_h^T V_h  (split-8 over S)
// ---------------------------------------------------------------------------
#define KTV_SPLIT 8
#define KTV_CHUNK (SEQ / KTV_SPLIT)   /* 256 */

__global__ __launch_bounds__(256)
void ktv_gemm() {
    const int bh = blockIdx.x;
    const int b  = bh >> 4;
    const int h  = bh & 15;
    const int sbeg = blockIdx.y * KTV_CHUNK;

    const float* Kb = g_K + (size_t)b * SEQ * HIDDEN + h * HEAD_DIM;
    const float* Vb = g_V + (size_t)b * SEQ * HIDDEN + h * HEAD_DIM;

    __shared__ float Ks[64 * 64];
    __shared__ float Vs[64 * 64];

    const int tid = threadIdx.x;
    const int tx  = tid & 15;
    const int ty  = tid >> 4;

    float acc[4][4];
#pragma unroll
    for (int i = 0; i < 4; i++)
#pragma unroll
        for (int j = 0; j < 4; j++) acc[i][j] = 0.0f;

    for (int s0 = sbeg; s0 < sbeg + KTV_CHUNK; s0 += 64) {
#pragma unroll
        for (int t = 0; t < 4; t++) {
            int e   = (tid + t * 256) * 4;
            int row = e >> 6;
            int col = e & 63;
            *reinterpret_cast<float4*>(&Ks[e]) =
                *reinterpret_cast<const float4*>(Kb + (size_t)(s0 + row) * HIDDEN + col);
            *reinterpret_cast<float4*>(&Vs[e]) =
                *reinterpret_cast<const float4*>(Vb + (size_t)(s0 + row) * HIDDEN + col);
        }
        __syncthreads();

#pragma unroll 4
        for (int ss = 0; ss < 64; ss++) {
            float kv[4], vv[4];
            *reinterpret_cast<float4*>(kv) = *reinterpret_cast<const float4*>(&Ks[ss * 64 + ty * 4]);
            *reinterpret_cast<float4*>(vv) = *reinterpret_cast<const float4*>(&Vs[ss * 64 + tx * 4]);
#pragma unroll
            for (int i = 0; i < 4; i++)
#pragma unroll
                for (int j = 0; j < 4; j++)
                    acc[i][j] = fmaf(kv[i], vv[j], acc[i][j]);
        }
        __syncthreads();
    }

    float* Mh = g_M + (size_t)bh * HEAD_DIM * HEAD_DIM;
#pragma unroll
    for (int i = 0; i < 4; i++)
#pragma unroll
        for (int j = 0; j < 4; j++)
            atomicAdd(&Mh[(ty * 4 + i) * 64 + tx * 4 + j], acc[i][j]);
}

// ---------------------------------------------------------------------------
// Kernel 3: out_h = scale * Q_h @ M_h
// ---------------------------------------------------------------------------
__global__ __launch_bounds__(256)
void out_gemm(float* __restrict__ out) {
    const int bh = blockIdx.y;
    const int b  = bh >> 4;
    const int h  = bh & 15;
    const int s0 = blockIdx.x * 64;
    const float scale = 0.125f;

    const float* Qb = g_Q + (size_t)b * SEQ * HIDDEN + h * HEAD_DIM;
    const float* Mh = g_M + (size_t)bh * HEAD_DIM * HEAD_DIM;

    __shared__ float Qs[64 * 64];
    __shared__ float Ms[64 * 64];

    const int tid = threadIdx.x;
    const int tx  = tid & 15;
    const int ty  = tid >> 4;

#pragma unroll
    for (int t = 0; t < 4; t++) {
        int e   = (tid + t * 256) * 4;
        int row = e >> 6;
        int col = e & 63;
        *reinterpret_cast<float4*>(&Qs[e]) =
            *reinterpret_cast<const float4*>(Qb + (size_t)(s0 + row) * HIDDEN + col);
        *reinterpret_cast<float4*>(&Ms[e]) = *reinterpret_cast<const float4*>(&Mh[e]);
    }
    __syncthreads();

    float acc[4][4];
#pragma unroll
    for (int i = 0; i < 4; i++)
#pragma unroll
        for (int j = 0; j < 4; j++) acc[i][j] = 0.0f;

#pragma unroll 4
    for (int k = 0; k < 64; k++) {
        float qv[4], mv[4];
#pragma unroll
        for (int i = 0; i < 4; i++) qv[i] = Qs[(ty * 4 + i) * 64 + k];
        *reinterpret_cast<float4*>(mv) = *reinterpret_cast<const float4*>(&Ms[k * 64 + tx * 4]);
#pragma unroll
        for (int i = 0; i < 4; i++)
#pragma unroll
            for (int j = 0; j < 4; j++)
                acc[i][j] = fmaf(qv[i], mv[j], acc[i][j]);
    }

#pragma unroll
    for (int i = 0; i < 4; i++) {
        float4 v = make_float4(scale * acc[i][0], scale * acc[i][1],
                               scale * acc[i][2], scale * acc[i][3]);
        *reinterpret_cast<float4*>(out + (size_t)(b * SEQ + s0 + ty * 4 + i) * HIDDEN
                                   + h * HEAD_DIM + tx * 4) = v;
    }
}

// ---------------------------------------------------------------------------
extern "C" void kernel_launch(void* const* d_in, const int* in_sizes, int n_in,
                              void* d_out, int out_size) {
    (void)in_sizes; (void)n_in; (void)out_size;
    const float* query = (const float*)d_in[0];
    const float* key   = (const float*)d_in[1];
    const float* value = (const float*)d_in[2];
    const float* q_w   = (const float*)d_in[3];
    const float* q_b   = (const float*)d_in[4];
    const float* k_w   = (const float*)d_in[5];
    const float* k_b   = (const float*)d_in[6];
    const float* v_w   = (const float*)d_in[7];
    const float* v_b   = (const float*)d_in[8];
    float* out = (float*)d_out;

    void *qp, *kp, *vp;
    cudaGetSymbolAddress(&qp, g_Q);
    cudaGetSymbolAddress(&kp, g_K);
    cudaGetSymbolAddress(&vp, g_V);

    cudaFuncSetAttribute(proj_gemm_mma, cudaFuncAttributeMaxDynamicSharedMemorySize, SMEM_DYN);

    Ptr3 xin; xin.p[0] = query; xin.p[1] = key; xin.p[2] = value;
    Ptr3 win; win.p[0] = q_w;   win.p[1] = k_w; win.p[2] = v_w;

    // 1. fp32 -> fp16 splits (A: hi+lo, B: hi only)
    dim3 xgrid((unsigned)((size_t)MROWS * HIDDEN / 4 / 256), 3);
    split_x_kernel<<<xgrid, 256>>>(xin);
    split_w_kernel<<<dim3(HIDDEN / 32, HIDDEN / 32, 3), 256>>>(win);
    zero_m_kernel<<<(BATCH * HEADS * HEAD_DIM * HEAD_DIM) / 256, 256>>>();

    // 2. Tensor-core projections (fp16 mma, 2 terms, BK=64 double-buffered)
    GemmArgs ga;
    ga.Bv[0] = q_b; ga.Bv[1] = k_b; ga.Bv[2] = v_b;
    ga.Y[0] = (float*)qp; ga.Y[1] = (float*)kp; ga.Y[2] = (float*)vp;
    proj_gemm_mma<<<dim3(HIDDEN / 256, MROWS / 128, 3), 256, SMEM_DYN>>>(ga);

    // 3. Small batched GEMMs
    ktv_gemm<<<dim3(BATCH * HEADS, KTV_SPLIT), 256>>>();
    out_gemm<<<dim3(SEQ / 64, BATCH * HEADS), 256>>>(out);
}